// round 16
// baseline (speedup 1.0000x reference)
#include <cuda_runtime.h>
#include <cuda_fp16.h>
#include <mma.h>

using namespace nvcuda;

#define NMAX 50000
#define EMAX 1600000
#define MMAX (EMAX + NMAX)

// ---- scratch (static __device__ globals; referenced ONLY from device code) ----
__device__ __half g_Wh[256 * 256];       // W in fp16
__device__ __half g_xph[NMAX * 256];     // x @ W  (fp16)
__device__ __half g_hh[NMAX * 256];      // GAT output (fp16)
__device__ float  g_asrc[NMAX * 4];
__device__ float  g_adst[NMAX * 4];
__device__ int    g_count[NMAX];
__device__ int    g_off[NMAX];
__device__ int    g_cursor[NMAX];
__device__ int4   g_slot[MMAX];          // bucketed-by-dst: {src, dst, eid, 0}
__device__ int    g_total;

__device__ __forceinline__ float lrelu(float x, float s) { return fmaxf(x, s * x); }

// packed f32x2 helpers (FFMA2 path — ptxas never emits from plain C++)
#define PACKF2(d, lo, hi) asm("mov.b64 %0, {%1, %2};" : "=l"(d) : "f"(lo), "f"(hi))
#define UNPACKF2(lo, hi, s) asm("mov.b64 {%0, %1}, %2;" : "=f"(lo), "=f"(hi) : "l"(s))
#define MULF2(d, a, b) asm("mul.rn.f32x2 %0, %1, %2;" : "=l"(d) : "l"(a), "l"(b))
#define FMAF2(d, a, b, c) asm("fma.rn.f32x2 %0, %1, %2, %3;" : "=l"(d) : "l"(a), "l"(b), "l"(c))

// ============================================================================
// prep: W fp32 -> fp16
// ============================================================================
__global__ void convert_w_kernel(const float* __restrict__ Wm, int n8) {
    int i = blockIdx.x * blockDim.x + threadIdx.x;
    if (i >= n8) return;
    float4 a = *(const float4*)(Wm + i * 8);
    float4 b = *(const float4*)(Wm + i * 8 + 4);
    __half2 h[4];
    h[0] = __float22half2_rn(make_float2(a.x, a.y));
    h[1] = __float22half2_rn(make_float2(a.z, a.w));
    h[2] = __float22half2_rn(make_float2(b.x, b.y));
    h[3] = __float22half2_rn(make_float2(b.z, b.w));
    *(uint4*)(g_Wh + i * 8) = *(uint4*)h;
}

// zero attention-dot accumulators (GEMM epilogue atomically accumulates)
__global__ void zero_attn_kernel(int n4) {
    int i = blockIdx.x * blockDim.x + threadIdx.x;
    if (i < n4) { g_asrc[i] = 0.f; g_adst[i] = 0.f; }
}

// ============================================================================
// counting-sort prep
// ============================================================================
__global__ void init_count_kernel(int n) {
    int i = blockIdx.x * blockDim.x + threadIdx.x;
    if (i == 0) g_total = 0;
    if (i < n) g_count[i] = 1;   // self loop pre-counted
}

__global__ void hist_kernel(const int* __restrict__ ei, int e) {
    int i = blockIdx.x * blockDim.x + threadIdx.x;
    if (i < e) atomicAdd(&g_count[ei[e + i]], 1);
}

// multi-block scan: intra-block exclusive scan + atomic block base.
__global__ void scan_block_kernel(int n) {
    __shared__ int wsum[32];
    __shared__ int wbase[32];
    __shared__ int s_base;
    int tid = threadIdx.x;
    int lane = tid & 31, wid = tid >> 5;
    int idx = blockIdx.x * 1024 + tid;
    int v = (idx < n) ? g_count[idx] : 0;
    int x = v;
#pragma unroll
    for (int o = 1; o < 32; o <<= 1) {
        int y = __shfl_up_sync(0xffffffffu, x, o);
        if (lane >= o) x += y;
    }
    if (lane == 31) wsum[wid] = x;
    __syncthreads();
    if (wid == 0) {
        int wv = wsum[lane];
        int wx = wv;
#pragma unroll
        for (int o = 1; o < 32; o <<= 1) {
            int y = __shfl_up_sync(0xffffffffu, wx, o);
            if (lane >= o) wx += y;
        }
        wbase[lane] = wx - wv;
        if (lane == 31) s_base = atomicAdd(&g_total, wx);
    }
    __syncthreads();
    int excl = (x - v) + wbase[wid] + s_base;
    if (idx < n) { g_off[idx] = excl; g_cursor[idx] = excl; }
}

__global__ void scatter_kernel(const int* __restrict__ ei, int e, int n) {
    int m = blockIdx.x * blockDim.x + threadIdx.x;
    if (m >= e + n) return;
    int src, dst, eid;
    if (m < e) { src = ei[m]; dst = ei[e + m]; eid = m; }
    else       { src = m - e; dst = m - e; eid = -1; }
    int p = atomicAdd(&g_cursor[dst], 1);
    g_slot[p] = make_int4(src, dst, eid, 0);   // single STG.128
}

// ============================================================================
// GEMM: xp = X @ W via WMMA + FUSED attention dots from fp32 accumulators.
// (identical to R15 passing version)
// ============================================================================
#define SA_HALVES (128 * 72)
#define SB_HALVES (64 * 136)
#define GEMM_SMEM ((SA_HALVES + SB_HALVES) * 2)   // 35840 bytes

__global__ __launch_bounds__(512, 2)
void gemm_wmma_kernel(const float* __restrict__ X,
                      const float* __restrict__ att_s, const float* __restrict__ att_d,
                      int M) {
    extern __shared__ char dsm[];
    __half* sA = (__half*)dsm;                       // 18432 B
    __half* sB = (__half*)(dsm + SA_HALVES * 2);     // 17408 B
    float*  sC = (float*)dsm;                        // epilogue alias
    int tid = threadIdx.x;
    int wid = tid >> 5, lane = tid & 31;
    int warpM = wid >> 2, warpN = wid & 3;           // 4 x 4 warps
    int rowBase = blockIdx.x << 7;
    int colBase = blockIdx.y << 7;

    wmma::fragment<wmma::accumulator, 16, 16, 16, float> acc[2][2];
#pragma unroll
    for (int mt = 0; mt < 2; mt++)
#pragma unroll
        for (int nt = 0; nt < 2; nt++) wmma::fill_fragment(acc[mt][nt], 0.0f);

    int lrow = tid >> 2;
    int lq = (tid & 3) << 4;
    int arow = rowBase + lrow;
    if (arow >= M) arow = M - 1;                     // clamp; stores guarded below
    const float* gArow = X + (size_t)arow * 256 + lq;
    __half* stA = sA + lrow * 72 + lq;

    int brow = tid >> 3;                             // 0..63
    int bq = (tid & 7) << 4;                         // 0..112
    __half* stB = sB + brow * 136 + bq;

    for (int kc = 0; kc < 4; kc++) {
        float4 f0 = *(const float4*)(gArow + kc * 64);
        float4 f1 = *(const float4*)(gArow + kc * 64 + 4);
        float4 f2 = *(const float4*)(gArow + kc * 64 + 8);
        float4 f3 = *(const float4*)(gArow + kc * 64 + 12);
        const __half* gB = g_Wh + (size_t)(kc * 64 + brow) * 256 + colBase + bq;
        uint4 bv0 = *(const uint4*)gB;
        uint4 bv1 = *(const uint4*)(gB + 8);
        __half2 hv[8];
        hv[0] = __float22half2_rn(make_float2(f0.x, f0.y));
        hv[1] = __float22half2_rn(make_float2(f0.z, f0.w));
        hv[2] = __float22half2_rn(make_float2(f1.x, f1.y));
        hv[3] = __float22half2_rn(make_float2(f1.z, f1.w));
        hv[4] = __float22half2_rn(make_float2(f2.x, f2.y));
        hv[5] = __float22half2_rn(make_float2(f2.z, f2.w));
        hv[6] = __float22half2_rn(make_float2(f3.x, f3.y));
        hv[7] = __float22half2_rn(make_float2(f3.z, f3.w));
        __syncthreads();
        *(uint4*)stA = *(uint4*)&hv[0];
        *(uint4*)(stA + 8) = *(uint4*)&hv[4];
        *(uint4*)stB = bv0;
        *(uint4*)(stB + 8) = bv1;
        __syncthreads();
#pragma unroll
        for (int ks = 0; ks < 4; ks++) {
            wmma::fragment<wmma::matrix_a, 16, 16, 16, __half, wmma::row_major> af[2];
            wmma::fragment<wmma::matrix_b, 16, 16, 16, __half, wmma::row_major> bf[2];
#pragma unroll
            for (int mt = 0; mt < 2; mt++)
                wmma::load_matrix_sync(af[mt], sA + (warpM * 32 + mt * 16) * 72 + ks * 16, 72);
#pragma unroll
            for (int nt = 0; nt < 2; nt++)
                wmma::load_matrix_sync(bf[nt], sB + (ks * 16) * 136 + warpN * 32 + nt * 16, 136);
#pragma unroll
            for (int mt = 0; mt < 2; mt++)
#pragma unroll
                for (int nt = 0; nt < 2; nt++)
                    wmma::mma_sync(acc[mt][nt], af[mt], bf[nt], acc[mt][nt]);
        }
    }
    __syncthreads();                                 // before sC aliases sA/sB

    // ---- epilogue: fp16 store + fused attention partial dots ----
    float* myC = sC + wid * 384;                     // 16 rows x 24 floats
    int erow = lane >> 1;
    int ecol = (lane & 1) << 3;
    int head = (colBase >> 6) + (warpN >> 1);
    int hcb = (warpN & 1) * 32;                      // col offset within head

    float aws[16], awd[16];
#pragma unroll
    for (int nt2 = 0; nt2 < 2; nt2++)
#pragma unroll
        for (int j = 0; j < 8; j++) {
            int col = head * 64 + hcb + nt2 * 16 + ecol + j;
            aws[nt2 * 8 + j] = att_s[col];
            awd[nt2 * 8 + j] = att_d[col];
        }
    float ssac[2] = {0.f, 0.f}, sdac[2] = {0.f, 0.f};

#pragma unroll
    for (int mt = 0; mt < 2; mt++)
#pragma unroll
        for (int nt = 0; nt < 2; nt++) {
            wmma::store_matrix_sync(myC, acc[mt][nt], 24, wmma::mem_row_major);
            __syncwarp();
            const float* p = myC + erow * 24 + ecol;
            __half2 hx[4];
            hx[0] = __float22half2_rn(make_float2(p[0], p[1]));
            hx[1] = __float22half2_rn(make_float2(p[2], p[3]));
            hx[2] = __float22half2_rn(make_float2(p[4], p[5]));
            hx[3] = __float22half2_rn(make_float2(p[6], p[7]));
            float dss = 0.f, dsd = 0.f;
#pragma unroll
            for (int j = 0; j < 8; j++) {
                dss += p[j] * aws[nt * 8 + j];
                dsd += p[j] * awd[nt * 8 + j];
            }
            ssac[mt] += dss;
            sdac[mt] += dsd;
            int gm = rowBase + warpM * 32 + mt * 16 + erow;
            int gn = colBase + warpN * 32 + nt * 16 + ecol;
            if (gm < M)
                *(uint4*)(g_xph + (size_t)gm * 256 + gn) = *(uint4*)hx;
            __syncwarp();
        }

#pragma unroll
    for (int mt = 0; mt < 2; mt++) {
        float s2 = ssac[mt] + __shfl_xor_sync(0xffffffffu, ssac[mt], 1);
        float d2 = sdac[mt] + __shfl_xor_sync(0xffffffffu, sdac[mt], 1);
        int gm = rowBase + warpM * 32 + mt * 16 + erow;
        if ((lane & 1) == 0 && gm < M) {
            atomicAdd(&g_asrc[gm * 4 + head], s2);
            atomicAdd(&g_adst[gm * 4 + head], d2);
        }
    }
}

// ============================================================================
// per-dst segment softmax + weighted aggregate + bias + leaky(0.01). Warp/dst.
// Batched index loads, own-head exp, 8-edge unroll (8 gather chains in flight).
// ============================================================================
__global__ void aggregate_kernel(const float* __restrict__ bias, int n) {
    int w = (blockIdx.x * blockDim.x + threadIdx.x) >> 5;
    int lane = threadIdx.x & 31;
    if (w >= n) return;
    int start = g_off[w];
    int deg = g_count[w];
    int hmine = lane >> 3;                     // this lane's head
    float ad_m = g_adst[(w << 2) + hmine];
    int c0 = lane << 3;

    float A[8];
#pragma unroll
    for (int j = 0; j < 8; j++) A[j] = 0.f;
    float dsum = 0.f;

    for (int base = 0; base < deg; base += 32) {
        int cnt = min(32, deg - base);
        int lidx = base + lane;
        int idx = g_slot[start + (lidx < deg ? lidx : deg - 1)].x;
        int j = 0;
        for (; j + 8 <= cnt; j += 8) {
            int s[8];
#pragma unroll
            for (int q = 0; q < 8; q++) s[q] = __shfl_sync(0xffffffffu, idx, j + q);
            float v[8];
#pragma unroll
            for (int q = 0; q < 8; q++) v[q] = g_asrc[(s[q] << 2) + hmine];
            uint4 hv[8];
#pragma unroll
            for (int q = 0; q < 8; q++)
                hv[q] = *(const uint4*)(g_xph + (size_t)s[q] * 256 + c0);
            float wg[8];
#pragma unroll
            for (int q = 0; q < 8; q++) {
                wg[q] = __expf(lrelu(v[q] + ad_m, 0.2f));
                dsum += wg[q];
            }
#pragma unroll
            for (int q = 0; q < 8; q++) {
                const __half2* h2 = (const __half2*)&hv[q];
#pragma unroll
                for (int k = 0; k < 4; k++) {
                    float2 f = __half22float2(h2[k]);
                    A[2 * k]     += wg[q] * f.x;
                    A[2 * k + 1] += wg[q] * f.y;
                }
            }
        }
        for (; j + 4 <= cnt; j += 4) {
            int s0 = __shfl_sync(0xffffffffu, idx, j);
            int s1 = __shfl_sync(0xffffffffu, idx, j + 1);
            int s2 = __shfl_sync(0xffffffffu, idx, j + 2);
            int s3 = __shfl_sync(0xffffffffu, idx, j + 3);
            float v0 = g_asrc[(s0 << 2) + hmine];
            float v1 = g_asrc[(s1 << 2) + hmine];
            float v2 = g_asrc[(s2 << 2) + hmine];
            float v3 = g_asrc[(s3 << 2) + hmine];
            uint4 hv0 = *(const uint4*)(g_xph + (size_t)s0 * 256 + c0);
            uint4 hv1 = *(const uint4*)(g_xph + (size_t)s1 * 256 + c0);
            uint4 hv2 = *(const uint4*)(g_xph + (size_t)s2 * 256 + c0);
            uint4 hv3 = *(const uint4*)(g_xph + (size_t)s3 * 256 + c0);
            float w0 = __expf(lrelu(v0 + ad_m, 0.2f));
            float w1 = __expf(lrelu(v1 + ad_m, 0.2f));
            float w2 = __expf(lrelu(v2 + ad_m, 0.2f));
            float w3 = __expf(lrelu(v3 + ad_m, 0.2f));
            dsum += (w0 + w1) + (w2 + w3);
            const __half2* h0 = (const __half2*)&hv0;
            const __half2* h1 = (const __half2*)&hv1;
            const __half2* h2 = (const __half2*)&hv2;
            const __half2* h3 = (const __half2*)&hv3;
#pragma unroll
            for (int k = 0; k < 4; k++) {
                float2 f0 = __half22float2(h0[k]);
                float2 f1 = __half22float2(h1[k]);
                float2 f2 = __half22float2(h2[k]);
                float2 f3 = __half22float2(h3[k]);
                A[2 * k]     += (w0 * f0.x + w1 * f1.x) + (w2 * f2.x + w3 * f3.x);
                A[2 * k + 1] += (w0 * f0.y + w1 * f1.y) + (w2 * f2.y + w3 * f3.y);
            }
        }
        for (; j < cnt; j++) {
            int s = __shfl_sync(0xffffffffu, idx, j);
            float v = g_asrc[(s << 2) + hmine];
            uint4 hv = *(const uint4*)(g_xph + (size_t)s * 256 + c0);
            float wg = __expf(lrelu(v + ad_m, 0.2f));
            dsum += wg;
            const __half2* h2 = (const __half2*)&hv;
#pragma unroll
            for (int k = 0; k < 4; k++) {
                float2 f = __half22float2(h2[k]);
                A[2 * k]     += wg * f.x;
                A[2 * k + 1] += wg * f.y;
            }
        }
    }

    float inv = 1.0f / (dsum + 1e-16f);        // identical across the head's lanes
    float4 b0 = *(const float4*)(bias + c0);
    float4 b1 = *(const float4*)(bias + c0 + 4);
    float o_[8];
    o_[0] = lrelu(A[0] * inv + b0.x, 0.01f);
    o_[1] = lrelu(A[1] * inv + b0.y, 0.01f);
    o_[2] = lrelu(A[2] * inv + b0.z, 0.01f);
    o_[3] = lrelu(A[3] * inv + b0.w, 0.01f);
    o_[4] = lrelu(A[4] * inv + b1.x, 0.01f);
    o_[5] = lrelu(A[5] * inv + b1.y, 0.01f);
    o_[6] = lrelu(A[6] * inv + b1.z, 0.01f);
    o_[7] = lrelu(A[7] * inv + b1.w, 0.01f);
    __half2 ho[4];
    ho[0] = __float22half2_rn(make_float2(o_[0], o_[1]));
    ho[1] = __float22half2_rn(make_float2(o_[2], o_[3]));
    ho[2] = __float22half2_rn(make_float2(o_[4], o_[5]));
    ho[3] = __float22half2_rn(make_float2(o_[6], o_[7]));
    *(uint4*)(g_hh + (size_t)w * 256 + c0) = *(uint4*)ho;
}

// ============================================================================
// edge scores: contiguous chunk per warp, register-cached h[dst], 4 edges per
// group on the f32x2 FMA pipe, SOFTWARE-PIPELINED: next group's slots + src
// rows prefetched during current group's compute + reduction.
// ============================================================================
__global__ void edge_score_kernel(const float* __restrict__ fc1W, const float* __restrict__ fc1b,
                                  float* __restrict__ out, int total) {
    int lane = threadIdx.x & 31;
    int warp = (blockIdx.x * blockDim.x + threadIdx.x) >> 5;
    int nwarps = (gridDim.x * blockDim.x) >> 5;
    int chunk = (total + nwarps - 1) / nwarps;
    int mbeg = warp * chunk;
    int mend = min(total, mbeg + chunk);
    if (mbeg >= mend) return;
    int c0 = lane << 3;

    unsigned long long wpk[4][3];
#pragma unroll
    for (int k = 0; k < 4; k++)
#pragma unroll
        for (int j = 0; j < 3; j++) {
            float lo = 0.5f * fc1W[(c0 + 2 * k) * 3 + j];
            float hi = 0.5f * fc1W[(c0 + 2 * k + 1) * 3 + j];
            PACKF2(wpk[k][j], lo, hi);
        }
    float b0 = fc1b[0], b1 = fc1b[1], b2 = fc1b[2];

    int prev_d = -1;
    uint4 ud = make_uint4(0, 0, 0, 0);
    int m = mbeg;

    int4 sl[4];
    uint4 us[4];
    if (m + 4 <= mend) {
#pragma unroll
        for (int q = 0; q < 4; q++) sl[q] = g_slot[m + q];
#pragma unroll
        for (int q = 0; q < 4; q++)
            us[q] = *(const uint4*)(g_hh + (size_t)sl[q].x * 256 + c0);
    }

    for (; m + 4 <= mend; m += 4) {
        // prefetch next group (slots + src rows) before current compute
        int4 sln[4];
        uint4 usn[4];
        bool nxt = (m + 8 <= mend);
        if (nxt) {
#pragma unroll
            for (int q = 0; q < 4; q++) sln[q] = g_slot[m + 4 + q];
#pragma unroll
            for (int q = 0; q < 4; q++)
                usn[q] = *(const uint4*)(g_hh + (size_t)sln[q].x * 256 + c0);
        }

        uint4 udq[4];
#pragma unroll
        for (int q = 0; q < 4; q++) {
            if (sl[q].y != prev_d) {           // warp-uniform
                ud = *(const uint4*)(g_hh + (size_t)sl[q].y * 256 + c0);
                prev_d = sl[q].y;
            }
            udq[q] = ud;
        }

        float a[4][3];
#pragma unroll
        for (int q = 0; q < 4; q++) {
            const __half2* hs2 = (const __half2*)&us[q];
            const __half2* hd2 = (const __half2*)&udq[q];
            unsigned long long apk0 = 0, apk1 = 0, apk2 = 0;
#pragma unroll
            for (int k = 0; k < 4; k++) {
                float2 fs = __half22float2(hs2[k]);
                float2 fd = __half22float2(hd2[k]);
                unsigned long long fspk, fdpk, rpk;
                PACKF2(fspk, fs.x, fs.y);
                PACKF2(fdpk, fd.x, fd.y);
                MULF2(rpk, fspk, fdpk);
                FMAF2(apk0, rpk, wpk[k][0], apk0);
                FMAF2(apk1, rpk, wpk[k][1], apk1);
                FMAF2(apk2, rpk, wpk[k][2], apk2);
            }
            float lo, hi;
            UNPACKF2(lo, hi, apk0); a[q][0] = lo + hi;
            UNPACKF2(lo, hi, apk1); a[q][1] = lo + hi;
            UNPACKF2(lo, hi, apk2); a[q][2] = lo + hi;
        }
#pragma unroll
        for (int o = 16; o; o >>= 1)
#pragma unroll
            for (int q = 0; q < 4; q++) {
                a[q][0] += __shfl_xor_sync(0xffffffffu, a[q][0], o);
                a[q][1] += __shfl_xor_sync(0xffffffffu, a[q][1], o);
                a[q][2] += __shfl_xor_sync(0xffffffffu, a[q][2], o);
            }
        if (lane == 0) {
#pragma unroll
            for (int q = 0; q < 4; q++)
                if (sl[q].z >= 0) {
                    out[sl[q].z * 3 + 0] = a[q][0] + b0;
                    out[sl[q].z * 3 + 1] = a[q][1] + b1;
                    out[sl[q].z * 3 + 2] = a[q][2] + b2;
                }
        }
        if (nxt) {
#pragma unroll
            for (int q = 0; q < 4; q++) { sl[q] = sln[q]; us[q] = usn[q]; }
        }
    }
    // tail (<4 slots)
    for (; m < mend; m++) {
        int4 slt = g_slot[m];
        uint4 ust = *(const uint4*)(g_hh + (size_t)slt.x * 256 + c0);
        if (slt.y != prev_d) {
            ud = *(const uint4*)(g_hh + (size_t)slt.y * 256 + c0);
            prev_d = slt.y;
        }
        const __half2* hs2 = (const __half2*)&ust;
        const __half2* hd2 = (const __half2*)&ud;
        unsigned long long apk0 = 0, apk1 = 0, apk2 = 0;
#pragma unroll
        for (int k = 0; k < 4; k++) {
            float2 fs = __half22float2(hs2[k]);
            float2 fd = __half22float2(hd2[k]);
            unsigned long long fspk, fdpk, rpk;
            PACKF2(fspk, fs.x, fs.y);
            PACKF2(fdpk, fd.x, fd.y);
            MULF2(rpk, fspk, fdpk);
            FMAF2(apk0, rpk, wpk[k][0], apk0);
            FMAF2(apk1, rpk, wpk[k][1], apk1);
            FMAF2(apk2, rpk, wpk[k][2], apk2);
        }
        float lo, hi, a0, a1, a2;
        UNPACKF2(lo, hi, apk0); a0 = lo + hi;
        UNPACKF2(lo, hi, apk1); a1 = lo + hi;
        UNPACKF2(lo, hi, apk2); a2 = lo + hi;
#pragma unroll
        for (int o = 16; o; o >>= 1) {
            a0 += __shfl_xor_sync(0xffffffffu, a0, o);
            a1 += __shfl_xor_sync(0xffffffffu, a1, o);
            a2 += __shfl_xor_sync(0xffffffffu, a2, o);
        }
        if (lane == 0 && slt.z >= 0) {
            out[slt.z * 3 + 0] = a0 + b0;
            out[slt.z * 3 + 1] = a1 + b1;
            out[slt.z * 3 + 2] = a2 + b2;
        }
    }
}

// ============================================================================
extern "C" void kernel_launch(void* const* d_in, const int* in_sizes, int n_in,
                              void* d_out, int out_size) {
    const float* x       = (const float*)d_in[0];
    const int*   ei      = (const int*)d_in[1];
    const float* Wm      = (const float*)d_in[2];
    const float* att_src = (const float*)d_in[3];
    const float* att_dst = (const float*)d_in[4];
    const float* bias    = (const float*)d_in[5];
    const float* fc1W    = (const float*)d_in[6];
    const float* fc1b    = (const float*)d_in[7];
    float* out = (float*)d_out;

    int n = in_sizes[0] / 256;   // nodes
    int e = in_sizes[1] / 2;     // edges

    static cudaStream_t sB = nullptr;
    static cudaEvent_t evFork = nullptr, evJoin = nullptr;
    if (sB == nullptr) {
        cudaStreamCaptureStatus st = cudaStreamCaptureStatusNone;
        cudaStreamIsCapturing(cudaStreamLegacy, &st);
        if (st == cudaStreamCaptureStatusNone) {
            cudaStreamCreateWithFlags(&sB, cudaStreamNonBlocking);
            cudaEventCreateWithFlags(&evFork, cudaEventDisableTiming);
            cudaEventCreateWithFlags(&evJoin, cudaEventDisableTiming);
        }
    }

    dim3 ggrid((n + 127) / 128, 2);

    if (sB != nullptr) {
        cudaEventRecord(evFork, 0);
        cudaStreamWaitEvent(sB, evFork, 0);

        convert_w_kernel<<<(256 * 32 + 255) / 256, 256>>>(Wm, 256 * 32);   // 1 (main)
        zero_attn_kernel<<<(n * 4 + 255) / 256, 256>>>(n * 4);             // 2 (main)
        init_count_kernel<<<(n + 255) / 256, 256, 0, sB>>>(n);             // 3 (side)
        gemm_wmma_kernel<<<ggrid, 512, GEMM_SMEM>>>(x, att_src, att_dst, n); // 4 (main, profiled)
        hist_kernel<<<(e + 255) / 256, 256, 0, sB>>>(ei, e);               // 5 (side)
        scan_block_kernel<<<(n + 1023) / 1024, 1024, 0, sB>>>(n);          // 6 (side)
        scatter_kernel<<<(e + n + 255) / 256, 256, 0, sB>>>(ei, e, n);     // 7 (side)
        cudaEventRecord(evJoin, sB);

        cudaStreamWaitEvent(0, evJoin, 0);     // join before aggregate
        aggregate_kernel<<<(n * 32 + 255) / 256, 256>>>(bias, n);          // 8
        edge_score_kernel<<<2048, 256>>>(fc1W, fc1b, out, e + n);          // 9
    } else {
        convert_w_kernel<<<(256 * 32 + 255) / 256, 256>>>(Wm, 256 * 32);
        zero_attn_kernel<<<(n * 4 + 255) / 256, 256>>>(n * 4);
        init_count_kernel<<<(n + 255) / 256, 256>>>(n);
        gemm_wmma_kernel<<<ggrid, 512, GEMM_SMEM>>>(x, att_src, att_dst, n);
        hist_kernel<<<(e + 255) / 256, 256>>>(ei, e);
        scan_block_kernel<<<(n + 1023) / 1024, 1024>>>(n);
        scatter_kernel<<<(e + n + 255) / 256, 256>>>(ei, e, n);
        aggregate_kernel<<<(n * 32 + 255) / 256, 256>>>(bias, n);
        edge_score_kernel<<<2048, 256>>>(fc1W, fc1b, out, e + n);
    }
}

// round 17
// speedup vs baseline: 1.0320x; 1.0320x over previous
#include <cuda_runtime.h>
#include <cuda_fp16.h>
#include <mma.h>

using namespace nvcuda;

#define NMAX 50000
#define EMAX 1600000
#define MMAX (EMAX + NMAX)

// ---- scratch (static __device__ globals; referenced ONLY from device code) ----
__device__ __half g_Wh[256 * 256];       // W in fp16
__device__ __half g_xph[NMAX * 256];     // x @ W  (fp16)
__device__ __half g_hh[NMAX * 256];      // GAT output (fp16)
__device__ float  g_asrc[NMAX * 4];
__device__ float  g_adst[NMAX * 4];
__device__ int    g_count[NMAX];
__device__ int    g_off[NMAX];
__device__ int    g_cursor[NMAX];
__device__ int4   g_slot[MMAX];          // bucketed-by-dst: {src, dst, eid, 0}
__device__ int    g_ssrc[MMAX];          // bucketed-by-dst: src only (4B stream)
__device__ int    g_total;

__device__ __forceinline__ float lrelu(float x, float s) { return fmaxf(x, s * x); }

// packed f32x2 helpers (FFMA2 path — ptxas never emits from plain C++)
#define PACKF2(d, lo, hi) asm("mov.b64 %0, {%1, %2};" : "=l"(d) : "f"(lo), "f"(hi))
#define UNPACKF2(lo, hi, s) asm("mov.b64 {%0, %1}, %2;" : "=f"(lo), "=f"(hi) : "l"(s))
#define MULF2(d, a, b) asm("mul.rn.f32x2 %0, %1, %2;" : "=l"(d) : "l"(a), "l"(b))
#define FMAF2(d, a, b, c) asm("fma.rn.f32x2 %0, %1, %2, %3;" : "=l"(d) : "l"(a), "l"(b), "l"(c))

// ============================================================================
// prep: W fp32 -> fp16
// ============================================================================
__global__ void convert_w_kernel(const float* __restrict__ Wm, int n8) {
    int i = blockIdx.x * blockDim.x + threadIdx.x;
    if (i >= n8) return;
    float4 a = *(const float4*)(Wm + i * 8);
    float4 b = *(const float4*)(Wm + i * 8 + 4);
    __half2 h[4];
    h[0] = __float22half2_rn(make_float2(a.x, a.y));
    h[1] = __float22half2_rn(make_float2(a.z, a.w));
    h[2] = __float22half2_rn(make_float2(b.x, b.y));
    h[3] = __float22half2_rn(make_float2(b.z, b.w));
    *(uint4*)(g_Wh + i * 8) = *(uint4*)h;
}

// zero attention-dot accumulators (GEMM epilogue atomically accumulates)
__global__ void zero_attn_kernel(int n4) {
    int i = blockIdx.x * blockDim.x + threadIdx.x;
    if (i < n4) { g_asrc[i] = 0.f; g_adst[i] = 0.f; }
}

// ============================================================================
// counting-sort prep
// ============================================================================
__global__ void init_count_kernel(int n) {
    int i = blockIdx.x * blockDim.x + threadIdx.x;
    if (i == 0) g_total = 0;
    if (i < n) g_count[i] = 1;   // self loop pre-counted
}

__global__ void hist_kernel(const int* __restrict__ ei, int e) {
    int i = blockIdx.x * blockDim.x + threadIdx.x;
    if (i < e) atomicAdd(&g_count[ei[e + i]], 1);
}

// multi-block scan: intra-block exclusive scan + atomic block base.
__global__ void scan_block_kernel(int n) {
    __shared__ int wsum[32];
    __shared__ int wbase[32];
    __shared__ int s_base;
    int tid = threadIdx.x;
    int lane = tid & 31, wid = tid >> 5;
    int idx = blockIdx.x * 1024 + tid;
    int v = (idx < n) ? g_count[idx] : 0;
    int x = v;
#pragma unroll
    for (int o = 1; o < 32; o <<= 1) {
        int y = __shfl_up_sync(0xffffffffu, x, o);
        if (lane >= o) x += y;
    }
    if (lane == 31) wsum[wid] = x;
    __syncthreads();
    if (wid == 0) {
        int wv = wsum[lane];
        int wx = wv;
#pragma unroll
        for (int o = 1; o < 32; o <<= 1) {
            int y = __shfl_up_sync(0xffffffffu, wx, o);
            if (lane >= o) wx += y;
        }
        wbase[lane] = wx - wv;
        if (lane == 31) s_base = atomicAdd(&g_total, wx);
    }
    __syncthreads();
    int excl = (x - v) + wbase[wid] + s_base;
    if (idx < n) { g_off[idx] = excl; g_cursor[idx] = excl; }
}

__global__ void scatter_kernel(const int* __restrict__ ei, int e, int n) {
    int m = blockIdx.x * blockDim.x + threadIdx.x;
    if (m >= e + n) return;
    int src, dst, eid;
    if (m < e) { src = ei[m]; dst = ei[e + m]; eid = m; }
    else       { src = m - e; dst = m - e; eid = -1; }
    int p = atomicAdd(&g_cursor[dst], 1);
    g_slot[p] = make_int4(src, dst, eid, 0);   // 16B for edge kernel
    g_ssrc[p] = src;                            // 4B stream for aggregate
}

// ============================================================================
// GEMM: xp = X @ W via WMMA + FUSED attention dots from fp32 accumulators.
// (identical to R15 passing version)
// ============================================================================
#define SA_HALVES (128 * 72)
#define SB_HALVES (64 * 136)
#define GEMM_SMEM ((SA_HALVES + SB_HALVES) * 2)   // 35840 bytes

__global__ __launch_bounds__(512, 2)
void gemm_wmma_kernel(const float* __restrict__ X,
                      const float* __restrict__ att_s, const float* __restrict__ att_d,
                      int M) {
    extern __shared__ char dsm[];
    __half* sA = (__half*)dsm;                       // 18432 B
    __half* sB = (__half*)(dsm + SA_HALVES * 2);     // 17408 B
    float*  sC = (float*)dsm;                        // epilogue alias
    int tid = threadIdx.x;
    int wid = tid >> 5, lane = tid & 31;
    int warpM = wid >> 2, warpN = wid & 3;           // 4 x 4 warps
    int rowBase = blockIdx.x << 7;
    int colBase = blockIdx.y << 7;

    wmma::fragment<wmma::accumulator, 16, 16, 16, float> acc[2][2];
#pragma unroll
    for (int mt = 0; mt < 2; mt++)
#pragma unroll
        for (int nt = 0; nt < 2; nt++) wmma::fill_fragment(acc[mt][nt], 0.0f);

    int lrow = tid >> 2;
    int lq = (tid & 3) << 4;
    int arow = rowBase + lrow;
    if (arow >= M) arow = M - 1;                     // clamp; stores guarded below
    const float* gArow = X + (size_t)arow * 256 + lq;
    __half* stA = sA + lrow * 72 + lq;

    int brow = tid >> 3;                             // 0..63
    int bq = (tid & 7) << 4;                         // 0..112
    __half* stB = sB + brow * 136 + bq;

    for (int kc = 0; kc < 4; kc++) {
        float4 f0 = *(const float4*)(gArow + kc * 64);
        float4 f1 = *(const float4*)(gArow + kc * 64 + 4);
        float4 f2 = *(const float4*)(gArow + kc * 64 + 8);
        float4 f3 = *(const float4*)(gArow + kc * 64 + 12);
        const __half* gB = g_Wh + (size_t)(kc * 64 + brow) * 256 + colBase + bq;
        uint4 bv0 = *(const uint4*)gB;
        uint4 bv1 = *(const uint4*)(gB + 8);
        __half2 hv[8];
        hv[0] = __float22half2_rn(make_float2(f0.x, f0.y));
        hv[1] = __float22half2_rn(make_float2(f0.z, f0.w));
        hv[2] = __float22half2_rn(make_float2(f1.x, f1.y));
        hv[3] = __float22half2_rn(make_float2(f1.z, f1.w));
        hv[4] = __float22half2_rn(make_float2(f2.x, f2.y));
        hv[5] = __float22half2_rn(make_float2(f2.z, f2.w));
        hv[6] = __float22half2_rn(make_float2(f3.x, f3.y));
        hv[7] = __float22half2_rn(make_float2(f3.z, f3.w));
        __syncthreads();
        *(uint4*)stA = *(uint4*)&hv[0];
        *(uint4*)(stA + 8) = *(uint4*)&hv[4];
        *(uint4*)stB = bv0;
        *(uint4*)(stB + 8) = bv1;
        __syncthreads();
#pragma unroll
        for (int ks = 0; ks < 4; ks++) {
            wmma::fragment<wmma::matrix_a, 16, 16, 16, __half, wmma::row_major> af[2];
            wmma::fragment<wmma::matrix_b, 16, 16, 16, __half, wmma::row_major> bf[2];
#pragma unroll
            for (int mt = 0; mt < 2; mt++)
                wmma::load_matrix_sync(af[mt], sA + (warpM * 32 + mt * 16) * 72 + ks * 16, 72);
#pragma unroll
            for (int nt = 0; nt < 2; nt++)
                wmma::load_matrix_sync(bf[nt], sB + (ks * 16) * 136 + warpN * 32 + nt * 16, 136);
#pragma unroll
            for (int mt = 0; mt < 2; mt++)
#pragma unroll
                for (int nt = 0; nt < 2; nt++)
                    wmma::mma_sync(acc[mt][nt], af[mt], bf[nt], acc[mt][nt]);
        }
    }
    __syncthreads();                                 // before sC aliases sA/sB

    // ---- epilogue: fp16 store + fused attention partial dots ----
    float* myC = sC + wid * 384;                     // 16 rows x 24 floats
    int erow = lane >> 1;
    int ecol = (lane & 1) << 3;
    int head = (colBase >> 6) + (warpN >> 1);
    int hcb = (warpN & 1) * 32;                      // col offset within head

    float aws[16], awd[16];
#pragma unroll
    for (int nt2 = 0; nt2 < 2; nt2++)
#pragma unroll
        for (int j = 0; j < 8; j++) {
            int col = head * 64 + hcb + nt2 * 16 + ecol + j;
            aws[nt2 * 8 + j] = att_s[col];
            awd[nt2 * 8 + j] = att_d[col];
        }
    float ssac[2] = {0.f, 0.f}, sdac[2] = {0.f, 0.f};

#pragma unroll
    for (int mt = 0; mt < 2; mt++)
#pragma unroll
        for (int nt = 0; nt < 2; nt++) {
            wmma::store_matrix_sync(myC, acc[mt][nt], 24, wmma::mem_row_major);
            __syncwarp();
            const float* p = myC + erow * 24 + ecol;
            __half2 hx[4];
            hx[0] = __float22half2_rn(make_float2(p[0], p[1]));
            hx[1] = __float22half2_rn(make_float2(p[2], p[3]));
            hx[2] = __float22half2_rn(make_float2(p[4], p[5]));
            hx[3] = __float22half2_rn(make_float2(p[6], p[7]));
            float dss = 0.f, dsd = 0.f;
#pragma unroll
            for (int j = 0; j < 8; j++) {
                dss += p[j] * aws[nt * 8 + j];
                dsd += p[j] * awd[nt * 8 + j];
            }
            ssac[mt] += dss;
            sdac[mt] += dsd;
            int gm = rowBase + warpM * 32 + mt * 16 + erow;
            int gn = colBase + warpN * 32 + nt * 16 + ecol;
            if (gm < M)
                *(uint4*)(g_xph + (size_t)gm * 256 + gn) = *(uint4*)hx;
            __syncwarp();
        }

#pragma unroll
    for (int mt = 0; mt < 2; mt++) {
        float s2 = ssac[mt] + __shfl_xor_sync(0xffffffffu, ssac[mt], 1);
        float d2 = sdac[mt] + __shfl_xor_sync(0xffffffffu, sdac[mt], 1);
        int gm = rowBase + warpM * 32 + mt * 16 + erow;
        if ((lane & 1) == 0 && gm < M) {
            atomicAdd(&g_asrc[gm * 4 + head], s2);
            atomicAdd(&g_adst[gm * 4 + head], d2);
        }
    }
}

// ============================================================================
// per-dst segment softmax + weighted aggregate + bias + leaky(0.01). Warp/dst.
// R15 version (4-edge unroll — empirically optimal), index stream now 4B/slot.
// ============================================================================
__global__ void aggregate_kernel(const float* __restrict__ bias, int n) {
    int w = (blockIdx.x * blockDim.x + threadIdx.x) >> 5;
    int lane = threadIdx.x & 31;
    if (w >= n) return;
    int start = g_off[w];
    int deg = g_count[w];
    int hmine = lane >> 3;                     // this lane's head
    float ad_m = g_adst[(w << 2) + hmine];
    int c0 = lane << 3;

    float A[8];
#pragma unroll
    for (int j = 0; j < 8; j++) A[j] = 0.f;
    float dsum = 0.f;

    for (int base = 0; base < deg; base += 32) {
        int cnt = min(32, deg - base);
        int lidx = base + lane;
        int idx = g_ssrc[start + (lidx < deg ? lidx : deg - 1)];
        int j = 0;
        for (; j + 4 <= cnt; j += 4) {
            int s0 = __shfl_sync(0xffffffffu, idx, j);
            int s1 = __shfl_sync(0xffffffffu, idx, j + 1);
            int s2 = __shfl_sync(0xffffffffu, idx, j + 2);
            int s3 = __shfl_sync(0xffffffffu, idx, j + 3);
            float v0 = g_asrc[(s0 << 2) + hmine];
            float v1 = g_asrc[(s1 << 2) + hmine];
            float v2 = g_asrc[(s2 << 2) + hmine];
            float v3 = g_asrc[(s3 << 2) + hmine];
            uint4 hv0 = *(const uint4*)(g_xph + (size_t)s0 * 256 + c0);
            uint4 hv1 = *(const uint4*)(g_xph + (size_t)s1 * 256 + c0);
            uint4 hv2 = *(const uint4*)(g_xph + (size_t)s2 * 256 + c0);
            uint4 hv3 = *(const uint4*)(g_xph + (size_t)s3 * 256 + c0);
            float w0 = __expf(lrelu(v0 + ad_m, 0.2f));
            float w1 = __expf(lrelu(v1 + ad_m, 0.2f));
            float w2 = __expf(lrelu(v2 + ad_m, 0.2f));
            float w3 = __expf(lrelu(v3 + ad_m, 0.2f));
            dsum += (w0 + w1) + (w2 + w3);
            const __half2* h0 = (const __half2*)&hv0;
            const __half2* h1 = (const __half2*)&hv1;
            const __half2* h2 = (const __half2*)&hv2;
            const __half2* h3 = (const __half2*)&hv3;
#pragma unroll
            for (int k = 0; k < 4; k++) {
                float2 f0 = __half22float2(h0[k]);
                float2 f1 = __half22float2(h1[k]);
                float2 f2 = __half22float2(h2[k]);
                float2 f3 = __half22float2(h3[k]);
                A[2 * k]     += (w0 * f0.x + w1 * f1.x) + (w2 * f2.x + w3 * f3.x);
                A[2 * k + 1] += (w0 * f0.y + w1 * f1.y) + (w2 * f2.y + w3 * f3.y);
            }
        }
        for (; j < cnt; j++) {
            int s = __shfl_sync(0xffffffffu, idx, j);
            float v = g_asrc[(s << 2) + hmine];
            uint4 hv = *(const uint4*)(g_xph + (size_t)s * 256 + c0);
            float wg = __expf(lrelu(v + ad_m, 0.2f));
            dsum += wg;
            const __half2* h2 = (const __half2*)&hv;
#pragma unroll
            for (int k = 0; k < 4; k++) {
                float2 f = __half22float2(h2[k]);
                A[2 * k]     += wg * f.x;
                A[2 * k + 1] += wg * f.y;
            }
        }
    }

    float inv = 1.0f / (dsum + 1e-16f);        // identical across the head's lanes
    float4 b0 = *(const float4*)(bias + c0);
    float4 b1 = *(const float4*)(bias + c0 + 4);
    float o_[8];
    o_[0] = lrelu(A[0] * inv + b0.x, 0.01f);
    o_[1] = lrelu(A[1] * inv + b0.y, 0.01f);
    o_[2] = lrelu(A[2] * inv + b0.z, 0.01f);
    o_[3] = lrelu(A[3] * inv + b0.w, 0.01f);
    o_[4] = lrelu(A[4] * inv + b1.x, 0.01f);
    o_[5] = lrelu(A[5] * inv + b1.y, 0.01f);
    o_[6] = lrelu(A[6] * inv + b1.z, 0.01f);
    o_[7] = lrelu(A[7] * inv + b1.w, 0.01f);
    __half2 ho[4];
    ho[0] = __float22half2_rn(make_float2(o_[0], o_[1]));
    ho[1] = __float22half2_rn(make_float2(o_[2], o_[3]));
    ho[2] = __float22half2_rn(make_float2(o_[4], o_[5]));
    ho[3] = __float22half2_rn(make_float2(o_[6], o_[7]));
    *(uint4*)(g_hh + (size_t)w * 256 + c0) = *(uint4*)ho;
}

// ============================================================================
// edge scores: contiguous chunk per warp, register-cached h[dst], 4 edges per
// iteration on the f32x2 FMA pipe. (R15 version — empirically optimal.)
// ============================================================================
__global__ void edge_score_kernel(const float* __restrict__ fc1W, const float* __restrict__ fc1b,
                                  float* __restrict__ out, int total) {
    int lane = threadIdx.x & 31;
    int warp = (blockIdx.x * blockDim.x + threadIdx.x) >> 5;
    int nwarps = (gridDim.x * blockDim.x) >> 5;
    int chunk = (total + nwarps - 1) / nwarps;
    int mbeg = warp * chunk;
    int mend = min(total, mbeg + chunk);
    if (mbeg >= mend) return;
    int c0 = lane << 3;

    unsigned long long wpk[4][3];
#pragma unroll
    for (int k = 0; k < 4; k++)
#pragma unroll
        for (int j = 0; j < 3; j++) {
            float lo = 0.5f * fc1W[(c0 + 2 * k) * 3 + j];
            float hi = 0.5f * fc1W[(c0 + 2 * k + 1) * 3 + j];
            PACKF2(wpk[k][j], lo, hi);
        }
    float b0 = fc1b[0], b1 = fc1b[1], b2 = fc1b[2];

    int prev_d = -1;
    uint4 ud = make_uint4(0, 0, 0, 0);
    int m = mbeg;
    for (; m + 4 <= mend; m += 4) {
        int4 sl[4];
        sl[0] = g_slot[m];
        sl[1] = g_slot[m + 1];
        sl[2] = g_slot[m + 2];
        sl[3] = g_slot[m + 3];
        uint4 us[4];
#pragma unroll
        for (int q = 0; q < 4; q++)
            us[q] = *(const uint4*)(g_hh + (size_t)sl[q].x * 256 + c0);
        uint4 udq[4];
#pragma unroll
        for (int q = 0; q < 4; q++) {
            if (sl[q].y != prev_d) {           // warp-uniform
                ud = *(const uint4*)(g_hh + (size_t)sl[q].y * 256 + c0);
                prev_d = sl[q].y;
            }
            udq[q] = ud;
        }

        float a[4][3];
#pragma unroll
        for (int q = 0; q < 4; q++) {
            const __half2* hs2 = (const __half2*)&us[q];
            const __half2* hd2 = (const __half2*)&udq[q];
            unsigned long long apk0 = 0, apk1 = 0, apk2 = 0;
#pragma unroll
            for (int k = 0; k < 4; k++) {
                float2 fs = __half22float2(hs2[k]);
                float2 fd = __half22float2(hd2[k]);
                unsigned long long fspk, fdpk, rpk;
                PACKF2(fspk, fs.x, fs.y);
                PACKF2(fdpk, fd.x, fd.y);
                MULF2(rpk, fspk, fdpk);
                FMAF2(apk0, rpk, wpk[k][0], apk0);
                FMAF2(apk1, rpk, wpk[k][1], apk1);
                FMAF2(apk2, rpk, wpk[k][2], apk2);
            }
            float lo, hi;
            UNPACKF2(lo, hi, apk0); a[q][0] = lo + hi;
            UNPACKF2(lo, hi, apk1); a[q][1] = lo + hi;
            UNPACKF2(lo, hi, apk2); a[q][2] = lo + hi;
        }
#pragma unroll
        for (int o = 16; o; o >>= 1)
#pragma unroll
            for (int q = 0; q < 4; q++) {
                a[q][0] += __shfl_xor_sync(0xffffffffu, a[q][0], o);
                a[q][1] += __shfl_xor_sync(0xffffffffu, a[q][1], o);
                a[q][2] += __shfl_xor_sync(0xffffffffu, a[q][2], o);
            }
        if (lane == 0) {
#pragma unroll
            for (int q = 0; q < 4; q++)
                if (sl[q].z >= 0) {
                    out[sl[q].z * 3 + 0] = a[q][0] + b0;
                    out[sl[q].z * 3 + 1] = a[q][1] + b1;
                    out[sl[q].z * 3 + 2] = a[q][2] + b2;
                }
        }
    }
    // tail (<4 slots)
    for (; m < mend; m++) {
        int4 sl = g_slot[m];
        uint4 us = *(const uint4*)(g_hh + (size_t)sl.x * 256 + c0);
        if (sl.y != prev_d) {
            ud = *(const uint4*)(g_hh + (size_t)sl.y * 256 + c0);
            prev_d = sl.y;
        }
        const __half2* hs2 = (const __half2*)&us;
        const __half2* hd2 = (const __half2*)&ud;
        unsigned long long apk0 = 0, apk1 = 0, apk2 = 0;
#pragma unroll
        for (int k = 0; k < 4; k++) {
            float2 fs = __half22float2(hs2[k]);
            float2 fd = __half22float2(hd2[k]);
            unsigned long long fspk, fdpk, rpk;
            PACKF2(fspk, fs.x, fs.y);
            PACKF2(fdpk, fd.x, fd.y);
            MULF2(rpk, fspk, fdpk);
            FMAF2(apk0, rpk, wpk[k][0], apk0);
            FMAF2(apk1, rpk, wpk[k][1], apk1);
            FMAF2(apk2, rpk, wpk[k][2], apk2);
        }
        float lo, hi, a0, a1, a2;
        UNPACKF2(lo, hi, apk0); a0 = lo + hi;
        UNPACKF2(lo, hi, apk1); a1 = lo + hi;
        UNPACKF2(lo, hi, apk2); a2 = lo + hi;
#pragma unroll
        for (int o = 16; o; o >>= 1) {
            a0 += __shfl_xor_sync(0xffffffffu, a0, o);
            a1 += __shfl_xor_sync(0xffffffffu, a1, o);
            a2 += __shfl_xor_sync(0xffffffffu, a2, o);
        }
        if (lane == 0 && sl.z >= 0) {
            out[sl.z * 3 + 0] = a0 + b0;
            out[sl.z * 3 + 1] = a1 + b1;
            out[sl.z * 3 + 2] = a2 + b2;
        }
    }
}

// ============================================================================
extern "C" void kernel_launch(void* const* d_in, const int* in_sizes, int n_in,
                              void* d_out, int out_size) {
    const float* x       = (const float*)d_in[0];
    const int*   ei      = (const int*)d_in[1];
    const float* Wm      = (const float*)d_in[2];
    const float* att_src = (const float*)d_in[3];
    const float* att_dst = (const float*)d_in[4];
    const float* bias    = (const float*)d_in[5];
    const float* fc1W    = (const float*)d_in[6];
    const float* fc1b    = (const float*)d_in[7];
    float* out = (float*)d_out;

    int n = in_sizes[0] / 256;   // nodes
    int e = in_sizes[1] / 2;     // edges

    static cudaStream_t sB = nullptr;
    static cudaEvent_t evFork = nullptr, evJoin = nullptr;
    if (sB == nullptr) {
        cudaStreamCaptureStatus st = cudaStreamCaptureStatusNone;
        cudaStreamIsCapturing(cudaStreamLegacy, &st);
        if (st == cudaStreamCaptureStatusNone) {
            cudaStreamCreateWithFlags(&sB, cudaStreamNonBlocking);
            cudaEventCreateWithFlags(&evFork, cudaEventDisableTiming);
            cudaEventCreateWithFlags(&evJoin, cudaEventDisableTiming);
        }
    }

    dim3 ggrid((n + 127) / 128, 2);

    if (sB != nullptr) {
        cudaEventRecord(evFork, 0);
        cudaStreamWaitEvent(sB, evFork, 0);

        convert_w_kernel<<<(256 * 32 + 255) / 256, 256>>>(Wm, 256 * 32);   // 1 (main)
        zero_attn_kernel<<<(n * 4 + 255) / 256, 256>>>(n * 4);             // 2 (main)
        init_count_kernel<<<(n + 255) / 256, 256, 0, sB>>>(n);             // 3 (side)
        gemm_wmma_kernel<<<ggrid, 512, GEMM_SMEM>>>(x, att_src, att_dst, n); // 4 (main, profiled)
        hist_kernel<<<(e + 255) / 256, 256, 0, sB>>>(ei, e);               // 5 (side)
        scan_block_kernel<<<(n + 1023) / 1024, 1024, 0, sB>>>(n);          // 6 (side)
        scatter_kernel<<<(e + n + 255) / 256, 256, 0, sB>>>(ei, e, n);     // 7 (side)
        cudaEventRecord(evJoin, sB);

        cudaStreamWaitEvent(0, evJoin, 0);     // join before aggregate
        aggregate_kernel<<<(n * 32 + 255) / 256, 256>>>(bias, n);          // 8
        edge_score_kernel<<<2048, 256>>>(fc1W, fc1b, out, e + n);          // 9
    } else {
        convert_w_kernel<<<(256 * 32 + 255) / 256, 256>>>(Wm, 256 * 32);
        zero_attn_kernel<<<(n * 4 + 255) / 256, 256>>>(n * 4);
        init_count_kernel<<<(n + 255) / 256, 256>>>(n);
        gemm_wmma_kernel<<<ggrid, 512, GEMM_SMEM>>>(x, att_src, att_dst, n);
        hist_kernel<<<(e + 255) / 256, 256>>>(ei, e);
        scan_block_kernel<<<(n + 1023) / 1024, 1024>>>(n);
        scatter_kernel<<<(e + n + 255) / 256, 256>>>(ei, e, n);
        aggregate_kernel<<<(n * 32 + 255) / 256, 256>>>(bias, n);
        edge_score_kernel<<<2048, 256>>>(fc1W, fc1b, out, e + n);
    }
}